// round 6
// baseline (speedup 1.0000x reference)
#include <cuda_runtime.h>
#include <cuda_fp16.h>
#include <cstdint>

// ============================================================================
// TTConv folded into ONE dense 256->256 3x3 conv, fp16 mma.sync implicit GEMM.
// Round 6: 2 CTAs/SM. CTA = M128 x N128 (2 rows x 64 cols), 256 thr, 91.4 KB
// smem. A staged per tap-triplet (dy row, 24.6 KB) 2-deep; Xs per icb 2-deep.
// ============================================================================

// ---------------- device scratch (no allocations allowed) -------------------
__device__ float  g_P[8 * 8 * 8 * 8 * 16];
__device__ float  g_G1f[4 * 4 * 9 * 16];            // [a][i][tap][u]
__device__ float  g_g1b[4 * 4 * 16];                // [a][i][u]
// A, pre-swizzled: [Mhalf 2][icb 8][tap 9][o_local 128][k 32(swizzled)]
__device__ __half g_Wsw[2 * 8 * 9 * 128 * 32];
__device__ float  g_beff[256];
__device__ __half g_Xh[8ull * 66 * 66 * 256];       // padded NHWC fp16

// ---------------- helpers ---------------------------------------------------
__device__ __forceinline__ uint32_t smem_u32(const void* p) {
    uint32_t a;
    asm("{ .reg .u64 t; cvta.to.shared.u64 t, %1; cvt.u32.u64 %0, t; }"
        : "=r"(a) : "l"(p));
    return a;
}

#define CP16(dst, src) \
    asm volatile("cp.async.ca.shared.global [%0], [%1], 16;" \
                 :: "r"(dst), "l"(src) : "memory")
#define CP_COMMIT() asm volatile("cp.async.commit_group;" ::: "memory")
#define CP_WAIT1()  asm volatile("cp.async.wait_group 1;" ::: "memory")
#define CP_WAIT0()  asm volatile("cp.async.wait_group 0;" ::: "memory")

#define LDSM4(r0, r1, r2, r3, addr) \
    asm volatile("ldmatrix.sync.aligned.m8n8.x4.shared.b16 {%0,%1,%2,%3}, [%4];" \
                 : "=r"(r0), "=r"(r1), "=r"(r2), "=r"(r3) : "r"(addr))

#define MMA16816(c, a0, a1, a2, a3, b0, b1) \
    asm volatile("mma.sync.aligned.m16n8k16.row.col.f32.f16.f16.f32 " \
                 "{%0,%1,%2,%3}, {%4,%5,%6,%7}, {%8,%9}, {%0,%1,%2,%3};" \
                 : "+f"((c)[0]), "+f"((c)[1]), "+f"((c)[2]), "+f"((c)[3]) \
                 : "r"(a0), "r"(a1), "r"(a2), "r"(a3), "r"(b0), "r"(b1))

// ---------------------------------------------------------------------------
// K1: P (blocks 0..255) + G1f/g1b (block 256)
// ---------------------------------------------------------------------------
__global__ void precompute_PG(const float* __restrict__ core1,
                              const float* __restrict__ core2,
                              const float* __restrict__ core3,
                              const float* __restrict__ conv_w,
                              const float* __restrict__ conv_b) {
    if (blockIdx.x < 256) {
        int idx = blockIdx.x * 256 + threadIdx.x;
        int u = idx & 15, k = (idx >> 4) & 7, j = (idx >> 7) & 7;
        int d = (idx >> 10) & 7, c = idx >> 13;
        float s = 0.f;
#pragma unroll
        for (int v = 0; v < 16; ++v)
            s += core2[(c * 16 + v) * 128 + u * 8 + j] * core3[d * 128 + v * 8 + k];
        g_P[idx] = s;
    } else {
        int t = threadIdx.x;
        for (int e = t; e < 2304; e += 256) {
            int u = e & 15, tap = (e >> 4) % 9, ai = e / 144;
            int a = ai >> 2, i = ai & 3;
            float s = 0.f;
#pragma unroll
            for (int r = 0; r < 16; ++r)
                s += core1[(a * 16 + u) * 64 + r * 4 + i] * conv_w[r * 9 + tap];
            g_G1f[e] = s;
        }
        if (t < 256) {
            int u = t & 15, ai = t >> 4;
            int a = ai >> 2, i = ai & 3;
            float s = 0.f;
#pragma unroll
            for (int r = 0; r < 16; ++r)
                s += core1[(a * 16 + u) * 64 + r * 4 + i] * conv_b[r];
            g_g1b[t] = s;
        }
    }
}

// ---------------------------------------------------------------------------
// K2: Weff (swizzled fp16 A) + beff, directly from P and G1f/g1b.
// ---------------------------------------------------------------------------
__global__ void precompute_Weff(int dummy) {
    int o = blockIdx.x, ic = threadIdx.x;
    int a = o >> 6, c = (o >> 3) & 7, d = o & 7;
    int i = ic >> 6, j = (ic >> 3) & 7, k = ic & 7;
    float Pu[16];
    const float* Pp = &g_P[(((c * 8 + d) * 8 + j) * 8 + k) * 16];
#pragma unroll
    for (int u = 0; u < 16; ++u) Pu[u] = Pp[u];

    int kk = ic & 31, icb = ic >> 5;
    int o_l = o & 127, mh = o >> 7;
    int swkk = ((((kk >> 3) ^ ((o_l >> 1) & 3)) << 3) | (kk & 7));
    const float* G1fp = &g_G1f[(a * 4 + i) * 144];
#pragma unroll
    for (int tap = 0; tap < 9; ++tap) {
        float s = 0.f;
#pragma unroll
        for (int u = 0; u < 16; ++u) s += G1fp[tap * 16 + u] * Pu[u];
        g_Wsw[((((size_t)mh * 8 + icb) * 9 + tap) * 128 + o_l) * 32 + swkk] =
            __float2half_rn(s);
    }
    const float* g1bp = &g_g1b[(a * 4 + i) * 16];
    float bp = 0.f;
#pragma unroll
    for (int u = 0; u < 16; ++u) bp += g1bp[u] * Pu[u];
    __shared__ float red[256];
    red[ic] = bp;
    __syncthreads();
    for (int s = 128; s > 0; s >>= 1) {
        if (ic < s) red[ic] += red[ic + s];
        __syncthreads();
    }
    if (ic == 0) g_beff[o] = red[0];
}

// ---------------------------------------------------------------------------
// K3: NCHW fp32 -> padded NHWC fp16 interior (y<64) + border zeroing (y==64)
// ---------------------------------------------------------------------------
__global__ void build_xpad(const float* __restrict__ X) {
    int y = blockIdx.x, icb = blockIdx.y, b = blockIdx.z;
    int tid = threadIdx.x;
    if (y == 64) {
        for (int e = tid; e < 1040; e += 256) {
            int p = e >> 2, q = e & 3;
            int yy, xx;
            if (p < 66)        { yy = 0;       xx = p; }
            else if (p < 132)  { yy = 65;      xx = p - 66; }
            else if (p < 196)  { yy = p - 131; xx = 0; }
            else               { yy = p - 195; xx = 65; }
            reinterpret_cast<uint4*>(
                g_Xh + (((size_t)b * 66 + yy) * 66 + xx) * 256 + icb * 32)[q] =
                make_uint4(0, 0, 0, 0);
        }
        return;
    }
    __shared__ float s[32 * 65];
    for (int i = tid; i < 2048; i += 256) {
        int icl = i >> 6, x = i & 63;
        s[icl * 65 + x] = X[(((size_t)b * 256 + icb * 32 + icl) * 64 + y) * 64 + x];
    }
    __syncthreads();
    for (int i = tid; i < 1024; i += 256) {
        int x = i >> 4, pr = i & 15;
        __half2 h = __floats2half2_rn(s[(2 * pr) * 65 + x], s[(2 * pr + 1) * 65 + x]);
        *reinterpret_cast<__half2*>(
            g_Xh + (((size_t)b * 66 + y + 1) * 66 + (x + 1)) * 256 + icb * 32 + 2 * pr) = h;
    }
}

// ---------------------------------------------------------------------------
// Main kernel. CTA: M128 x N128 (2 rows x 64 cols). 256 thr = 4(M) x 2(row).
// 24 pipeline steps = 8 icb x 3 dy-triplets; A 2-deep per triplet, Xs 2-deep
// per icb. One cp.async group per step, wait_group 1.
// Smem: A 2 x 24576 + Xs 2 x 21120 = 91392 -> 2 CTAs/SM.
// ---------------------------------------------------------------------------
static constexpr int A_TAP  = 8192;            // 128 rows x 64B
static constexpr int A_TRIP = 3 * A_TAP;       // 24576
static constexpr int XS_BUF = 21120;           // 264 rows x 80B
static constexpr int XS_OFF = 2 * A_TRIP;      // 49152
static constexpr int SMEM_DYN = XS_OFF + 2 * XS_BUF;  // 91392

__global__ __launch_bounds__(256, 2)
void conv_mma(float* __restrict__ out) {
    extern __shared__ char smc[];
    const uint32_t sb = smem_u32(smc);
    const int tid  = threadIdx.x;
    const int warp = tid >> 5, lane = tid & 31;
    const int warpM = warp >> 1;         // 0..3 -> o block of 32
    const int warpR = warp & 1;          // 0..1 -> output row within tile
    const int h0 = blockIdx.x * 2;
    const int b  = blockIdx.y;
    const int mh = blockIdx.z;
    const int Mbase = mh * 128;

    const int rowA = warpM * 32 + (lane & 15);
    const int hi   = lane >> 4;
    const int swA  = ((lane & 15) >> 1) & 3;
    const uint32_t aLane0 = (uint32_t)(rowA * 64 + ((hi ^ swA) << 4));
    const uint32_t aLane1 = (uint32_t)(rowA * 64 + (((2 + hi) ^ swA) << 4));
    const uint32_t xLane = (uint32_t)((((lane >> 4) & 1) * 8 + (lane & 7)) * 80 +
                                      ((lane >> 3) & 1) * 16);

    // ---- staging ----------------------------------------------------------
    auto stageA = [&](int step, int buf) {       // step = icb*3 + dy
        const int icb = step / 3, dy = step - icb * 3;
        const char* src = (const char*)(g_Wsw +
            (((size_t)mh * 8 + icb) * 9 + dy * 3) * 128 * 32);
        uint32_t dst = sb + buf * A_TRIP;
#pragma unroll
        for (int i = 0; i < 6; ++i) {            // 1536 x 16B
            int e = tid + i * 256;
            CP16(dst + e * 16, src + e * 16);
        }
    };
    auto stageXs = [&](int icb, int buf) {       // 264 rows x 4 x 16B
        uint32_t dst = sb + XS_OFF + buf * XS_BUF;
        const char* base = (const char*)g_Xh;
        for (int e = tid; e < 1056; e += 256) {
            int pix = e >> 2, c = e & 3;
            int yy = pix / 66, cc = pix - yy * 66;
            const char* src = base +
                ((((size_t)b * 66 + h0 + yy) * 66 + cc) * 256 + icb * 32) * 2 + c * 16;
            CP16(dst + pix * 80 + c * 16, src);
        }
    };

    float acc[2][8][4];
#pragma unroll
    for (int m = 0; m < 2; ++m)
#pragma unroll
        for (int n = 0; n < 8; ++n)
#pragma unroll
            for (int q = 0; q < 4; ++q) acc[m][n][q] = 0.f;

    // ---- prologue: groups for step 0 (with Xs0) and step 1 ----
    stageXs(0, 0); stageA(0, 0); CP_COMMIT();
    stageA(1, 1); CP_COMMIT();

    for (int step = 0; step < 24; ++step) {
        const int buf = step & 1;
        const int icb = step / 3, dy = step - icb * 3;
        if (step < 23) CP_WAIT1(); else CP_WAIT0();
        __syncthreads();

        const uint32_t aBase = sb + buf * A_TRIP;
        const uint32_t xRow  = sb + XS_OFF + (icb & 1) * XS_BUF +
                               (uint32_t)((warpR + dy) * 66 * 80) + xLane;

#pragma unroll
        for (int dx = 0; dx < 3; ++dx) {
            const uint32_t aT = aBase + dx * A_TAP;
            const uint32_t xT = xRow + (uint32_t)(dx * 80);
#pragma unroll
            for (int ks = 0; ks < 2; ++ks) {
                const uint32_t aAddr = aT + (ks ? aLane1 : aLane0);
                uint32_t a0, a1, a2, a3, e0, e1, e2, e3;
                LDSM4(a0, a1, a2, a3, aAddr);
                LDSM4(e0, e1, e2, e3, aAddr + 16 * 64);
#pragma unroll
                for (int p = 0; p < 4; ++p) {
                    uint32_t b0, b1, b2, b3;
                    LDSM4(b0, b1, b2, b3, xT + p * (16 * 80) + ks * 32);
                    MMA16816(acc[0][2 * p],     a0, a1, a2, a3, b0, b1);
                    MMA16816(acc[0][2 * p + 1], a0, a1, a2, a3, b2, b3);
                    MMA16816(acc[1][2 * p],     e0, e1, e2, e3, b0, b1);
                    MMA16816(acc[1][2 * p + 1], e0, e1, e2, e3, b2, b3);
                }
            }
        }
        __syncthreads();
        // stage step+2 (A), plus Xs for its icb if it starts a new icb
        if (step + 2 < 24) {
            int s2 = step + 2;
            if (s2 % 3 == 0) stageXs(s2 / 3, (s2 / 3) & 1);
            stageA(s2, s2 & 1);
            CP_COMMIT();
        }
    }

    // ---- epilogue: bias + direct float2 stores ----
    const int h = h0 + warpR;
#pragma unroll
    for (int mt = 0; mt < 2; ++mt) {
        int oLo = Mbase + warpM * 32 + mt * 16 + (lane >> 2);
        float bvLo = g_beff[oLo];
        float bvHi = g_beff[oLo + 8];
        float* rowLo = out + (((size_t)b * 256 + oLo) * 64 + h) * 64;
        float* rowHi = rowLo + (size_t)8 * 64 * 64;
#pragma unroll
        for (int nt = 0; nt < 8; ++nt) {
            int w = nt * 8 + (lane & 3) * 2;
            float2 vLo = make_float2(acc[mt][nt][0] + bvLo, acc[mt][nt][1] + bvLo);
            float2 vHi = make_float2(acc[mt][nt][2] + bvHi, acc[mt][nt][3] + bvHi);
            *reinterpret_cast<float2*>(rowLo + w) = vLo;
            *reinterpret_cast<float2*>(rowHi + w) = vHi;
        }
    }
}

// ---------------------------------------------------------------------------
extern "C" void kernel_launch(void* const* d_in, const int* in_sizes, int n_in,
                              void* d_out, int out_size) {
    const float *X = 0, *cw = 0, *cb = 0, *c1 = 0, *c2 = 0, *c3 = 0;
    for (int i = 0; i < n_in; ++i) {
        const float* p = (const float*)d_in[i];
        switch (in_sizes[i]) {
            case 8388608: X  = p; break;
            case 144:     cw = p; break;
            case 16:      cb = p; break;
            case 4096:    c1 = p; break;
            case 16384:   c2 = p; break;
            case 1024:    c3 = p; break;
            default: break;
        }
    }

    cudaFuncSetAttribute(conv_mma, cudaFuncAttributeMaxDynamicSharedMemorySize,
                         SMEM_DYN);

    precompute_PG<<<257, 256>>>(c1, c2, c3, cw, cb);
    precompute_Weff<<<256, 256>>>(0);
    build_xpad<<<dim3(65, 8, 8), 256>>>(X);

    conv_mma<<<dim3(32, 8, 2), 256, SMEM_DYN>>>((float*)d_out);
}

// round 7
// speedup vs baseline: 1.0437x; 1.0437x over previous
#include <cuda_runtime.h>
#include <cuda_fp16.h>
#include <cstdint>

// ============================================================================
// TTConv folded into ONE dense 256->256 3x3 conv, fp16 mma.sync implicit GEMM.
// Round 7: warp tile M64xN64 (1.0 smem-wavefront per MMA, was 1.5).
// CTA = M128 x N256 (4 rows x 64 cols), 256 thr = 2(M) x 4(row) warps.
// Pipeline identical to round 5: full-icb A staging, 2-deep cp.async.
// ============================================================================

// ---------------- device scratch (no allocations allowed) -------------------
__device__ float  g_P[8 * 8 * 8 * 8 * 16];
__device__ float  g_G1f[4 * 4 * 9 * 16];            // [a][i][tap][u]
__device__ float  g_g1b[4 * 4 * 16];                // [a][i][u]
// A, pre-swizzled: [Mhalf 2][icb 8][tap 9][o_local 128][k 32(swizzled)]
__device__ __half g_Wsw[2 * 8 * 9 * 128 * 32];
__device__ float  g_beff[256];
__device__ __half g_Xh[8ull * 66 * 66 * 256];       // padded NHWC fp16

// ---------------- helpers ---------------------------------------------------
__device__ __forceinline__ uint32_t smem_u32(const void* p) {
    uint32_t a;
    asm("{ .reg .u64 t; cvta.to.shared.u64 t, %1; cvt.u32.u64 %0, t; }"
        : "=r"(a) : "l"(p));
    return a;
}

#define CP16(dst, src) \
    asm volatile("cp.async.ca.shared.global [%0], [%1], 16;" \
                 :: "r"(dst), "l"(src) : "memory")
#define CP_COMMIT() asm volatile("cp.async.commit_group;" ::: "memory")
#define CP_WAIT1()  asm volatile("cp.async.wait_group 1;" ::: "memory")
#define CP_WAIT0()  asm volatile("cp.async.wait_group 0;" ::: "memory")

#define LDSM4(r0, r1, r2, r3, addr) \
    asm volatile("ldmatrix.sync.aligned.m8n8.x4.shared.b16 {%0,%1,%2,%3}, [%4];" \
                 : "=r"(r0), "=r"(r1), "=r"(r2), "=r"(r3) : "r"(addr))

#define MMA16816(c, a0, a1, a2, a3, b0, b1) \
    asm volatile("mma.sync.aligned.m16n8k16.row.col.f32.f16.f16.f32 " \
                 "{%0,%1,%2,%3}, {%4,%5,%6,%7}, {%8,%9}, {%0,%1,%2,%3};" \
                 : "+f"((c)[0]), "+f"((c)[1]), "+f"((c)[2]), "+f"((c)[3]) \
                 : "r"(a0), "r"(a1), "r"(a2), "r"(a3), "r"(b0), "r"(b1))

// ---------------------------------------------------------------------------
// K1: P (blocks 0..255) + G1f/g1b (block 256)
// ---------------------------------------------------------------------------
__global__ void precompute_PG(const float* __restrict__ core1,
                              const float* __restrict__ core2,
                              const float* __restrict__ core3,
                              const float* __restrict__ conv_w,
                              const float* __restrict__ conv_b) {
    if (blockIdx.x < 256) {
        int idx = blockIdx.x * 256 + threadIdx.x;
        int u = idx & 15, k = (idx >> 4) & 7, j = (idx >> 7) & 7;
        int d = (idx >> 10) & 7, c = idx >> 13;
        float s = 0.f;
#pragma unroll
        for (int v = 0; v < 16; ++v)
            s += core2[(c * 16 + v) * 128 + u * 8 + j] * core3[d * 128 + v * 8 + k];
        g_P[idx] = s;
    } else {
        int t = threadIdx.x;
        for (int e = t; e < 2304; e += 256) {
            int u = e & 15, tap = (e >> 4) % 9, ai = e / 144;
            int a = ai >> 2, i = ai & 3;
            float s = 0.f;
#pragma unroll
            for (int r = 0; r < 16; ++r)
                s += core1[(a * 16 + u) * 64 + r * 4 + i] * conv_w[r * 9 + tap];
            g_G1f[e] = s;
        }
        if (t < 256) {
            int u = t & 15, ai = t >> 4;
            int a = ai >> 2, i = ai & 3;
            float s = 0.f;
#pragma unroll
            for (int r = 0; r < 16; ++r)
                s += core1[(a * 16 + u) * 64 + r * 4 + i] * conv_b[r];
            g_g1b[t] = s;
        }
    }
}

// ---------------------------------------------------------------------------
// K2: Weff (swizzled fp16 A) + beff, directly from P and G1f/g1b.
// ---------------------------------------------------------------------------
__global__ void precompute_Weff(int dummy) {
    int o = blockIdx.x, ic = threadIdx.x;
    int a = o >> 6, c = (o >> 3) & 7, d = o & 7;
    int i = ic >> 6, j = (ic >> 3) & 7, k = ic & 7;
    float Pu[16];
    const float* Pp = &g_P[(((c * 8 + d) * 8 + j) * 8 + k) * 16];
#pragma unroll
    for (int u = 0; u < 16; ++u) Pu[u] = Pp[u];

    int kk = ic & 31, icb = ic >> 5;
    int o_l = o & 127, mh = o >> 7;
    int swkk = ((((kk >> 3) ^ ((o_l >> 1) & 3)) << 3) | (kk & 7));
    const float* G1fp = &g_G1f[(a * 4 + i) * 144];
#pragma unroll
    for (int tap = 0; tap < 9; ++tap) {
        float s = 0.f;
#pragma unroll
        for (int u = 0; u < 16; ++u) s += G1fp[tap * 16 + u] * Pu[u];
        g_Wsw[((((size_t)mh * 8 + icb) * 9 + tap) * 128 + o_l) * 32 + swkk] =
            __float2half_rn(s);
    }
    const float* g1bp = &g_g1b[(a * 4 + i) * 16];
    float bp = 0.f;
#pragma unroll
    for (int u = 0; u < 16; ++u) bp += g1bp[u] * Pu[u];
    __shared__ float red[256];
    red[ic] = bp;
    __syncthreads();
    for (int s = 128; s > 0; s >>= 1) {
        if (ic < s) red[ic] += red[ic + s];
        __syncthreads();
    }
    if (ic == 0) g_beff[o] = red[0];
}

// ---------------------------------------------------------------------------
// K3: NCHW fp32 -> padded NHWC fp16 interior (y<64) + border zeroing (y==64)
// ---------------------------------------------------------------------------
__global__ void build_xpad(const float* __restrict__ X) {
    int y = blockIdx.x, icb = blockIdx.y, b = blockIdx.z;
    int tid = threadIdx.x;
    if (y == 64) {
        for (int e = tid; e < 1040; e += 256) {
            int p = e >> 2, q = e & 3;
            int yy, xx;
            if (p < 66)        { yy = 0;       xx = p; }
            else if (p < 132)  { yy = 65;      xx = p - 66; }
            else if (p < 196)  { yy = p - 131; xx = 0; }
            else               { yy = p - 195; xx = 65; }
            reinterpret_cast<uint4*>(
                g_Xh + (((size_t)b * 66 + yy) * 66 + xx) * 256 + icb * 32)[q] =
                make_uint4(0, 0, 0, 0);
        }
        return;
    }
    __shared__ float s[32 * 65];
    for (int i = tid; i < 2048; i += 256) {
        int icl = i >> 6, x = i & 63;
        s[icl * 65 + x] = X[(((size_t)b * 256 + icb * 32 + icl) * 64 + y) * 64 + x];
    }
    __syncthreads();
    for (int i = tid; i < 1024; i += 256) {
        int x = i >> 4, pr = i & 15;
        __half2 h = __floats2half2_rn(s[(2 * pr) * 65 + x], s[(2 * pr + 1) * 65 + x]);
        *reinterpret_cast<__half2*>(
            g_Xh + (((size_t)b * 66 + y + 1) * 66 + (x + 1)) * 256 + icb * 32 + 2 * pr) = h;
    }
}

// ---------------------------------------------------------------------------
// Main kernel. CTA: M128 x N256 (4 rows x 64 cols). 256 thr = 2(M) x 4(row).
// Warp tile M64 x N64: per ks 8 LDSM4 -> 32 MMA (1.0 wf/MMA).
// Smem: A 2 x 73728 (full icb, 9 taps) + Xs 2 x 31680. 1 CTA/SM.
// ---------------------------------------------------------------------------
static constexpr int A_CH   = 8192;
static constexpr int A_BUF  = 9 * A_CH;        // 73728
static constexpr int XS_BUF = 31680;           // 396 rows x 80B
static constexpr int XS_OFF = 2 * A_BUF;       // 147456
static constexpr int SMEM_DYN = XS_OFF + 2 * XS_BUF;  // 210816

__global__ __launch_bounds__(256, 1)
void conv_mma(float* __restrict__ out) {
    extern __shared__ char smc[];
    const uint32_t sb = smem_u32(smc);
    const int tid  = threadIdx.x;
    const int warp = tid >> 5, lane = tid & 31;
    const int warpM = warp >> 2;         // 0..1 -> o block of 64
    const int warpR = warp & 3;          // 0..3 -> output row within tile
    const int h0 = blockIdx.x * 4;
    const int b  = blockIdx.y;
    const int mh = blockIdx.z;
    const int Mbase = mh * 128;

    // A ldmatrix addressing (swizzled 64B rows), warp rows warpM*64 + 0..63
    const int rowA = warpM * 64 + (lane & 15);
    const int hi   = lane >> 4;
    const int swA  = ((lane & 15) >> 1) & 3;
    const uint32_t aLane0 = (uint32_t)(rowA * 64 + ((hi ^ swA) << 4));
    const uint32_t aLane1 = (uint32_t)(rowA * 64 + (((2 + hi) ^ swA) << 4));
    const uint32_t xLane = (uint32_t)((((lane >> 4) & 1) * 8 + (lane & 7)) * 80 +
                                      ((lane >> 3) & 1) * 16);

    auto stageA = [&](int icb, int buf) {
        const char* src = (const char*)(g_Wsw + (((size_t)mh * 8 + icb) * 9) * 128 * 32);
        uint32_t dst = sb + buf * A_BUF;
#pragma unroll
        for (int i = 0; i < 18; ++i) {           // 4608 x 16B over 256 thr
            int e = tid + i * 256;
            CP16(dst + e * 16, src + e * 16);
        }
    };
    auto stageXs = [&](int icb, int buf) {
        uint32_t dst = sb + XS_OFF + buf * XS_BUF;
        const char* base = (const char*)g_Xh;
        for (int e = tid; e < 1584; e += 256) {
            int pix = e >> 2, c = e & 3;
            int yy = pix / 66, cc = pix - yy * 66;
            const char* src = base +
                ((((size_t)b * 66 + h0 + yy) * 66 + cc) * 256 + icb * 32) * 2 + c * 16;
            CP16(dst + pix * 80 + c * 16, src);
        }
    };

    float acc[4][8][4];
#pragma unroll
    for (int m = 0; m < 4; ++m)
#pragma unroll
        for (int n = 0; n < 8; ++n)
#pragma unroll
            for (int q = 0; q < 4; ++q) acc[m][n][q] = 0.f;

    stageXs(0, 0); stageA(0, 0); CP_COMMIT();
    stageXs(1, 1); stageA(1, 1); CP_COMMIT();

    for (int icb = 0; icb < 8; ++icb) {
        const int buf = icb & 1;
        if (icb < 7) CP_WAIT1(); else CP_WAIT0();
        __syncthreads();

        const uint32_t aBase = sb + buf * A_BUF;
        const uint32_t xBase = sb + XS_OFF + buf * XS_BUF;

#pragma unroll
        for (int tap = 0; tap < 9; ++tap) {
            const int dy = tap / 3, dx = tap - dy * 3;
            const uint32_t aT = aBase + tap * A_CH;
            const uint32_t xT = xBase + (uint32_t)(((warpR + dy) * 66 + dx) * 80) + xLane;

#pragma unroll
            for (int ks = 0; ks < 2; ++ks) {
                const uint32_t aAddr = aT + (ks ? aLane1 : aLane0);
                uint32_t af[4][4];
#pragma unroll
                for (int mt = 0; mt < 4; ++mt)
                    LDSM4(af[mt][0], af[mt][1], af[mt][2], af[mt][3],
                          aAddr + mt * (16 * 64));
#pragma unroll
                for (int p = 0; p < 4; ++p) {
                    uint32_t b0, b1, b2, b3;
                    LDSM4(b0, b1, b2, b3, xT + p * (16 * 80) + ks * 32);
#pragma unroll
                    for (int mt = 0; mt < 4; ++mt) {
                        MMA16816(acc[mt][2 * p],     af[mt][0], af[mt][1],
                                 af[mt][2], af[mt][3], b0, b1);
                        MMA16816(acc[mt][2 * p + 1], af[mt][0], af[mt][1],
                                 af[mt][2], af[mt][3], b2, b3);
                    }
                }
            }
        }
        __syncthreads();
        if (icb + 2 < 8) {
            stageXs(icb + 2, buf);
            stageA(icb + 2, buf);
            CP_COMMIT();
        }
    }

    // ---- epilogue: bias + direct float2 stores ----
    const int h = h0 + warpR;
#pragma unroll
    for (int mt = 0; mt < 4; ++mt) {
        int oLo = Mbase + warpM * 64 + mt * 16 + (lane >> 2);
        float bvLo = g_beff[oLo];
        float bvHi = g_beff[oLo + 8];
        float* rowLo = out + (((size_t)b * 256 + oLo) * 64 + h) * 64;
        float* rowHi = rowLo + (size_t)8 * 64 * 64;
#pragma unroll
        for (int nt = 0; nt < 8; ++nt) {
            int w = nt * 8 + (lane & 3) * 2;
            float2 vLo = make_float2(acc[mt][nt][0] + bvLo, acc[mt][nt][1] + bvLo);
            float2 vHi = make_float2(acc[mt][nt][2] + bvHi, acc[mt][nt][3] + bvHi);
            *reinterpret_cast<float2*>(rowLo + w) = vLo;
            *reinterpret_cast<float2*>(rowHi + w) = vHi;
        }
    }
}

// ---------------------------------------------------------------------------
extern "C" void kernel_launch(void* const* d_in, const int* in_sizes, int n_in,
                              void* d_out, int out_size) {
    const float *X = 0, *cw = 0, *cb = 0, *c1 = 0, *c2 = 0, *c3 = 0;
    for (int i = 0; i < n_in; ++i) {
        const float* p = (const float*)d_in[i];
        switch (in_sizes[i]) {
            case 8388608: X  = p; break;
            case 144:     cw = p; break;
            case 16:      cb = p; break;
            case 4096:    c1 = p; break;
            case 16384:   c2 = p; break;
            case 1024:    c3 = p; break;
            default: break;
        }
    }

    cudaFuncSetAttribute(conv_mma, cudaFuncAttributeMaxDynamicSharedMemorySize,
                         SMEM_DYN);

    precompute_PG<<<257, 256>>>(c1, c2, c3, cw, cb);
    precompute_Weff<<<256, 256>>>(0);
    build_xpad<<<dim3(65, 8, 8), 256>>>(X);

    conv_mma<<<dim3(16, 8, 2), 256, SMEM_DYN>>>((float*)d_out);
}